// round 1
// baseline (speedup 1.0000x reference)
#include <cuda_runtime.h>
#include <cuda_bf16.h>
#include <math.h>

// ---------------------------------------------------------------------------
// Two-hop GAT: fixed shapes
// ---------------------------------------------------------------------------
#define NN 50000
#define DD 512
#define HH 512
#define OO 256
#define EE 150000
#define NEG_SLOPE 0.2f
#define SEG_EPS 1e-16f

// ---------------------------------------------------------------------------
// Static device scratch (no allocations allowed)
// ---------------------------------------------------------------------------
__device__ float g_H1src[(size_t)NN * HH];
__device__ float g_H1dst[(size_t)NN * HH];
__device__ float g_agg1 [(size_t)NN * HH];
__device__ float g_h    [(size_t)NN * HH];
__device__ float g_H2src[(size_t)NN * OO];
__device__ float g_H2dst[(size_t)NN * OO];
__device__ float g_agg2 [(size_t)NN * OO];
__device__ float g_asrc [NN];
__device__ float g_adst [NN];
__device__ float g_m    [NN];
__device__ float g_s    [NN];

// ---------------------------------------------------------------------------
// SGEMM: C[M,Nc] = A[M,K] @ B[K,Nc]  (+bias, optional relu)
// 128x128 tile, BK=8, 256 threads, 8x8 microtile. Nc,K multiples of 128/8.
// ---------------------------------------------------------------------------
#define BM 128
#define BN 128
#define BK 8
#define TM 8
#define TN 8

__global__ __launch_bounds__(256, 2)
void sgemm_kernel(const float* __restrict__ A, const float* __restrict__ B,
                  float* __restrict__ C, int M, int Nc, int K,
                  const float* __restrict__ bias, int relu)
{
    __shared__ float As[BK][BM];
    __shared__ float Bs[BK][BN];

    const int bx = blockIdx.x;           // N tile
    const int by = blockIdx.y;           // M tile
    const int tid = threadIdx.x;
    const int tx = tid & 15;             // 0..15
    const int ty = tid >> 4;             // 0..15

    const int aRow  = tid >> 1;          // 0..127
    const int aK4   = (tid & 1) * 4;     // 0 or 4
    const int bRow  = tid >> 5;          // 0..7
    const int bCol4 = (tid & 31) * 4;

    const int rowBase = by * BM;
    const bool aValid = (rowBase + aRow) < M;
    const float* Aptr = A + (size_t)(aValid ? (rowBase + aRow) : 0) * K;
    const float* Bptr = B + (size_t)bRow * Nc + bx * BN + bCol4;

    float acc[TM][TN];
#pragma unroll
    for (int i = 0; i < TM; i++)
#pragma unroll
        for (int j = 0; j < TN; j++) acc[i][j] = 0.0f;

    for (int k0 = 0; k0 < K; k0 += BK) {
        float4 av = make_float4(0.f, 0.f, 0.f, 0.f);
        if (aValid) av = *(const float4*)(Aptr + k0 + aK4);
        As[aK4 + 0][aRow] = av.x;
        As[aK4 + 1][aRow] = av.y;
        As[aK4 + 2][aRow] = av.z;
        As[aK4 + 3][aRow] = av.w;

        float4 bv = *(const float4*)(Bptr + (size_t)k0 * Nc);
        *(float4*)&Bs[bRow][bCol4] = bv;

        __syncthreads();

#pragma unroll
        for (int k = 0; k < BK; ++k) {
            float aF[TM], bF[TN];
            float4 a0 = *(const float4*)&As[k][ty * TM];
            float4 a1 = *(const float4*)&As[k][ty * TM + 4];
            aF[0]=a0.x; aF[1]=a0.y; aF[2]=a0.z; aF[3]=a0.w;
            aF[4]=a1.x; aF[5]=a1.y; aF[6]=a1.z; aF[7]=a1.w;
            float4 b0 = *(const float4*)&Bs[k][tx * TN];
            float4 b1 = *(const float4*)&Bs[k][tx * TN + 4];
            bF[0]=b0.x; bF[1]=b0.y; bF[2]=b0.z; bF[3]=b0.w;
            bF[4]=b1.x; bF[5]=b1.y; bF[6]=b1.z; bF[7]=b1.w;
#pragma unroll
            for (int i = 0; i < TM; i++)
#pragma unroll
                for (int j = 0; j < TN; j++)
                    acc[i][j] = fmaf(aF[i], bF[j], acc[i][j]);
        }
        __syncthreads();
    }

#pragma unroll
    for (int i = 0; i < TM; i++) {
        int r = rowBase + ty * TM + i;
        if (r >= M) continue;
        float* Crow = C + (size_t)r * Nc + bx * BN + tx * TN;
#pragma unroll
        for (int j = 0; j < TN; j += 4) {
            int c = bx * BN + tx * TN + j;
            float4 v;
            v.x = acc[i][j + 0];
            v.y = acc[i][j + 1];
            v.z = acc[i][j + 2];
            v.w = acc[i][j + 3];
            if (bias) {
                v.x += bias[c + 0]; v.y += bias[c + 1];
                v.z += bias[c + 2]; v.w += bias[c + 3];
            }
            if (relu) {
                v.x = fmaxf(v.x, 0.f); v.y = fmaxf(v.y, 0.f);
                v.z = fmaxf(v.z, 0.f); v.w = fmaxf(v.w, 0.f);
            }
            *(float4*)(Crow + j) = v;
        }
    }
}

// ---------------------------------------------------------------------------
// alpha kernel: per node i, as[i] = dot(Hs[i,:], a_s), ad[i] = dot(Hd[i,:], a_d)
// one warp per node
// ---------------------------------------------------------------------------
__global__ void alpha_kernel(const float* __restrict__ Hs,
                             const float* __restrict__ Hd,
                             const float* __restrict__ a_s,
                             const float* __restrict__ a_d,
                             float* __restrict__ as_out,
                             float* __restrict__ ad_out,
                             int N, int C)
{
    int warp = (blockIdx.x * blockDim.x + threadIdx.x) >> 5;
    int lane = threadIdx.x & 31;
    if (warp >= N) return;
    const float* hs = Hs + (size_t)warp * C;
    const float* hd = Hd + (size_t)warp * C;
    float s1 = 0.f, s2 = 0.f;
    for (int c = lane * 4; c < C; c += 32 * 4) {
        float4 h1 = *(const float4*)(hs + c);
        float4 h2 = *(const float4*)(hd + c);
        float4 w1 = *(const float4*)(a_s + c);
        float4 w2 = *(const float4*)(a_d + c);
        s1 += h1.x*w1.x + h1.y*w1.y + h1.z*w1.z + h1.w*w1.w;
        s2 += h2.x*w2.x + h2.y*w2.y + h2.z*w2.z + h2.w*w2.w;
    }
#pragma unroll
    for (int o = 16; o; o >>= 1) {
        s1 += __shfl_xor_sync(0xFFFFFFFFu, s1, o);
        s2 += __shfl_xor_sync(0xFFFFFFFFu, s2, o);
    }
    if (lane == 0) { as_out[warp] = s1; ad_out[warp] = s2; }
}

// ---------------------------------------------------------------------------
// init kernels
// ---------------------------------------------------------------------------
__global__ void init_ms_kernel(float* __restrict__ m, float* __restrict__ s, int N)
{
    int i = blockIdx.x * blockDim.x + threadIdx.x;
    if (i < N) { m[i] = __int_as_float(0xFF800000); s[i] = 0.f; }
}

// agg[n,c] = 2*b[c]   (two gat_conv calls each add bias once)
__global__ void init_agg_kernel(float* __restrict__ agg, const float* __restrict__ b,
                                int N, int C)
{
    int idx = blockIdx.x * blockDim.x + threadIdx.x;
    int total = N * C;
    for (; idx < total; idx += gridDim.x * blockDim.x)
        agg[idx] = 2.0f * b[idx % C];
}

// ---------------------------------------------------------------------------
// edge passes
// ---------------------------------------------------------------------------
__device__ __forceinline__ float leaky(float v)
{
    return v > 0.f ? v : NEG_SLOPE * v;
}

__device__ __forceinline__ void atomicMaxFloat(float* addr, float val)
{
    // nonneg floats order like ints; neg floats order reversed as uints
    if (val >= 0.f) atomicMax((int*)addr, __float_as_int(val));
    else            atomicMin((unsigned int*)addr, __float_as_uint(val));
}

__global__ void edge_max_kernel(const int* __restrict__ src, const int* __restrict__ dst,
                                const float* __restrict__ as, const float* __restrict__ ad,
                                float* __restrict__ m, int E)
{
    int e = blockIdx.x * blockDim.x + threadIdx.x;
    if (e >= E) return;
    int si = src[e], di = dst[e];
    float v = leaky(as[si] + ad[di]);
    atomicMaxFloat(&m[di], v);
}

__global__ void edge_sum_kernel(const int* __restrict__ src, const int* __restrict__ dst,
                                const float* __restrict__ as, const float* __restrict__ ad,
                                const float* __restrict__ m, float* __restrict__ s, int E)
{
    int e = blockIdx.x * blockDim.x + threadIdx.x;
    if (e >= E) return;
    int si = src[e], di = dst[e];
    float v = leaky(as[si] + ad[di]);
    atomicAdd(&s[di], __expf(v - m[di]));
}

// one warp per edge: agg[dst,:] += alpha * H[src,:]
__global__ void edge_agg_kernel(const int* __restrict__ src, const int* __restrict__ dst,
                                const float* __restrict__ as, const float* __restrict__ ad,
                                const float* __restrict__ m, const float* __restrict__ s,
                                const float* __restrict__ H, float* __restrict__ agg,
                                int E, int C)
{
    int warp = (blockIdx.x * blockDim.x + threadIdx.x) >> 5;
    int lane = threadIdx.x & 31;
    if (warp >= E) return;
    int si = src[warp], di = dst[warp];
    float v = leaky(as[si] + ad[di]);
    float alpha = __expf(v - m[di]) / (s[di] + SEG_EPS);
    const float4* h4 = (const float4*)(H + (size_t)si * C);
    float* ag = agg + (size_t)di * C;
    int nvec = C >> 2;
    for (int c = lane; c < nvec; c += 32) {
        float4 hv = h4[c];
        atomicAdd(ag + 4 * c + 0, alpha * hv.x);
        atomicAdd(ag + 4 * c + 1, alpha * hv.y);
        atomicAdd(ag + 4 * c + 2, alpha * hv.z);
        atomicAdd(ag + 4 * c + 3, alpha * hv.w);
    }
}

// ---------------------------------------------------------------------------
// host-side helpers
// ---------------------------------------------------------------------------
static void run_sgemm(const float* A, const float* B, float* C, int M, int Nc, int K,
                      const float* bias, int relu)
{
    dim3 grid(Nc / BN, (M + BM - 1) / BM);
    sgemm_kernel<<<grid, 256>>>(A, B, C, M, Nc, K, bias, relu);
}

static void run_edge_softmax_agg(const int* ei, const float* asrc, const float* adst,
                                 float* m, float* s, const float* H, float* agg, int C)
{
    const int* src = ei;
    const int* dst = ei + EE;
    int nb1 = (EE + 255) / 256;
    init_ms_kernel<<<(NN + 255) / 256, 256>>>(m, s, NN);
    edge_max_kernel<<<nb1, 256>>>(src, dst, asrc, adst, m, EE);
    edge_sum_kernel<<<nb1, 256>>>(src, dst, asrc, adst, m, s, EE);
    int nbw = ((EE * 32) + 255) / 256;
    edge_agg_kernel<<<nbw, 256>>>(src, dst, asrc, adst, m, s, H, agg, EE, C);
}

extern "C" void kernel_launch(void* const* d_in, const int* in_sizes, int n_in,
                              void* d_out, int out_size)
{
    const float* x      = (const float*)d_in[0];
    const int*   ei1    = (const int*)  d_in[1];
    const int*   ei2    = (const int*)  d_in[2];
    const float* W1_src = (const float*)d_in[3];
    const float* W1_dst = (const float*)d_in[4];
    const float* a1_src = (const float*)d_in[5];
    const float* a1_dst = (const float*)d_in[6];
    const float* b1     = (const float*)d_in[7];
    const float* Wl1    = (const float*)d_in[8];
    const float* bl1    = (const float*)d_in[9];
    const float* W2_src = (const float*)d_in[10];
    const float* W2_dst = (const float*)d_in[11];
    const float* a2_src = (const float*)d_in[12];
    const float* a2_dst = (const float*)d_in[13];
    const float* b2     = (const float*)d_in[14];
    const float* Wl2    = (const float*)d_in[15];
    const float* bl2    = (const float*)d_in[16];
    float* out = (float*)d_out;

    // device scratch symbol addresses (host side)
    float *H1s, *H1d, *A1, *Hm, *H2s, *H2d, *A2, *as_, *ad_, *m_, *s_;
    cudaGetSymbolAddress((void**)&H1s, g_H1src);
    cudaGetSymbolAddress((void**)&H1d, g_H1dst);
    cudaGetSymbolAddress((void**)&A1,  g_agg1);
    cudaGetSymbolAddress((void**)&Hm,  g_h);
    cudaGetSymbolAddress((void**)&H2s, g_H2src);
    cudaGetSymbolAddress((void**)&H2d, g_H2dst);
    cudaGetSymbolAddress((void**)&A2,  g_agg2);
    cudaGetSymbolAddress((void**)&as_, g_asrc);
    cudaGetSymbolAddress((void**)&ad_, g_adst);
    cudaGetSymbolAddress((void**)&m_,  g_m);
    cudaGetSymbolAddress((void**)&s_,  g_s);

    // ---- Layer 1: conv1 over both edge sets (shared projections) ----
    run_sgemm(x, W1_src, H1s, NN, HH, DD, nullptr, 0);
    run_sgemm(x, W1_dst, H1d, NN, HH, DD, nullptr, 0);
    alpha_kernel<<<((NN * 32) + 255) / 256, 256>>>(H1s, H1d, a1_src, a1_dst, as_, ad_, NN, HH);
    init_agg_kernel<<<2048, 256>>>(A1, b1, NN, HH);
    run_edge_softmax_agg(ei1, as_, ad_, m_, s_, H1s, A1, HH);
    run_edge_softmax_agg(ei2, as_, ad_, m_, s_, H1s, A1, HH);

    // ---- lin1 + relu ----
    run_sgemm(A1, Wl1, Hm, NN, HH, HH, bl1, 1);

    // ---- Layer 2: conv2 over both edge sets ----
    run_sgemm(Hm, W2_src, H2s, NN, OO, HH, nullptr, 0);
    run_sgemm(Hm, W2_dst, H2d, NN, OO, HH, nullptr, 0);
    alpha_kernel<<<((NN * 32) + 255) / 256, 256>>>(H2s, H2d, a2_src, a2_dst, as_, ad_, NN, OO);
    init_agg_kernel<<<2048, 256>>>(A2, b2, NN, OO);
    run_edge_softmax_agg(ei1, as_, ad_, m_, s_, H2s, A2, OO);
    run_edge_softmax_agg(ei2, as_, ad_, m_, s_, H2s, A2, OO);

    // ---- lin2 -> output ----
    run_sgemm(A2, Wl2, out, NN, OO, OO, bl2, 0);
}

// round 5
// speedup vs baseline: 1.7294x; 1.7294x over previous
#include <cuda_runtime.h>
#include <cuda_bf16.h>
#include <cstdint>
#include <math.h>

// ---------------------------------------------------------------------------
// Two-hop GAT: fixed shapes
// ---------------------------------------------------------------------------
#define NN 50000
#define DD 512
#define HH 512
#define OO 256
#define EE 150000
#define NEG_SLOPE 0.2f
#define SEG_EPS 1e-16f

// ---------------------------------------------------------------------------
// Static device scratch (no allocations allowed)
// ---------------------------------------------------------------------------
__device__ float g_H1src[(size_t)NN * HH];
__device__ float g_H1dst[(size_t)NN * HH];
__device__ float g_agg1 [(size_t)NN * HH];
__device__ float g_h    [(size_t)NN * HH];
__device__ float g_H2src[(size_t)NN * OO];
__device__ float g_H2dst[(size_t)NN * OO];
__device__ float g_agg2 [(size_t)NN * OO];
__device__ float g_asrc [NN];
__device__ float g_adst [NN];
__device__ float g_m    [NN];
__device__ float g_s    [NN];
// bf16 split scratch: activations (hi/lo) and two transposed weight slots
__device__ __nv_bfloat16 g_xhi[(size_t)NN * HH];
__device__ __nv_bfloat16 g_xlo[(size_t)NN * HH];
__device__ __nv_bfloat16 g_wahi[HH * HH];
__device__ __nv_bfloat16 g_walo[HH * HH];
__device__ __nv_bfloat16 g_wbhi[HH * HH];
__device__ __nv_bfloat16 g_wblo[HH * HH];

// ---------------------------------------------------------------------------
// HMMA GEMM (mma.sync bf16, arch-portable): C[M,Nc] = A[M,K] @ Bt[Nc,K]^T
// A, Bt given as bf16 hi/lo splits; accum fp32; optional bias/relu fused.
// CTA tile 128x128, K-tile 64 (128B SMEM rows, SW128 swizzle), 8 warps.
// ---------------------------------------------------------------------------
#define SWZ(o) ((o) ^ (((o) >> 3) & 0x70))

#define LDSM4(r, addr) \
    asm volatile("ldmatrix.sync.aligned.m8n8.x4.shared.b16 {%0,%1,%2,%3}, [%4];" \
        : "=r"((r)[0]), "=r"((r)[1]), "=r"((r)[2]), "=r"((r)[3]) : "r"(addr))

#define MMA(c, a, b) \
    asm volatile("mma.sync.aligned.m16n8k16.row.col.f32.bf16.bf16.f32 " \
        "{%0,%1,%2,%3}, {%4,%5,%6,%7}, {%8,%9}, {%0,%1,%2,%3};" \
        : "+f"((c)[0]), "+f"((c)[1]), "+f"((c)[2]), "+f"((c)[3]) \
        : "r"((a)[0]), "r"((a)[1]), "r"((a)[2]), "r"((a)[3]), \
          "r"((b)[0]), "r"((b)[1]))

__device__ __forceinline__ uint32_t smem_u32(const void* p) {
    uint32_t a;
    asm("{ .reg .u64 t; cvta.to.shared.u64 t, %1; cvt.u32.u64 %0, t; }"
        : "=r"(a) : "l"(p));
    return a;
}

#define GSM_TOTAL 65536  // 4 x 16KB tiles (Ahi, Alo, Bhi, Blo)

__global__ __launch_bounds__(256, 2)
void hmma_gemm_kernel(const __nv_bfloat16* __restrict__ Ahi,
                      const __nv_bfloat16* __restrict__ Alo,
                      const __nv_bfloat16* __restrict__ Bhi,
                      const __nv_bfloat16* __restrict__ Blo,
                      float* __restrict__ C, int M, int Nc, int K,
                      const float* __restrict__ bias, int relu)
{
    extern __shared__ __align__(128) char smem[];
    const uint32_t sb = smem_u32(smem);
    const uint32_t sAh = sb, sAl = sb + 16384, sBh = sb + 32768, sBl = sb + 49152;

    const int tid  = threadIdx.x;
    const int lane = tid & 31;
    const int wid  = tid >> 5;
    const int m_off = (wid & 3) * 32;   // warp m-offset within CTA tile
    const int n_off = (wid >> 2) * 64;  // warp n-offset
    const int m0 = blockIdx.y * 128, n0 = blockIdx.x * 128;

    float acc[2][8][4];
#pragma unroll
    for (int i = 0; i < 2; i++)
#pragma unroll
        for (int j = 0; j < 8; j++)
#pragma unroll
            for (int l = 0; l < 4; l++) acc[i][j][l] = 0.0f;

    // global tile loads: each thread handles half a 128B row (64B = 4 x uint4)
    const int lr = tid >> 1, lh = tid & 1;
    const bool av = (m0 + lr) < M;
    const uint4* gAh = (const uint4*)(Ahi + (size_t)(av ? m0 + lr : 0) * K);
    const uint4* gAl = (const uint4*)(Alo + (size_t)(av ? m0 + lr : 0) * K);
    const uint4* gBh = (const uint4*)(Bhi + (size_t)(n0 + lr) * K);
    const uint4* gBl = (const uint4*)(Blo + (size_t)(n0 + lr) * K);

    // ldmatrix per-lane base byte offsets (logical; SWZ applied later)
    const uint32_t aRowB = (uint32_t)(m_off + (lane & 15)) * 128
                         + ((lane >> 4) & 1) * 16;
    const uint32_t bRowB = (uint32_t)(n_off + (lane & 7) + ((lane >> 4) & 1) * 8) * 128
                         + ((lane >> 3) & 1) * 16;

    const int nkt = K >> 6;
    for (int kt = 0; kt < nkt; ++kt) {
        if (kt) __syncthreads();
        const uint4 z = make_uint4(0, 0, 0, 0);
        const int kb = kt * 8 + lh * 4;
#pragma unroll
        for (int i = 0; i < 4; i++) {
            uint32_t d = SWZ((uint32_t)lr * 128 + lh * 64 + i * 16);
            *(uint4*)(smem + d)         = av ? gAh[kb + i] : z;
            *(uint4*)(smem + 16384 + d) = av ? gAl[kb + i] : z;
            *(uint4*)(smem + 32768 + d) = gBh[kb + i];
            *(uint4*)(smem + 49152 + d) = gBl[kb + i];
        }
        __syncthreads();

#pragma unroll
        for (int kk = 0; kk < 4; ++kk) {
            uint32_t ah[2][4], al[2][4];
#pragma unroll
            for (int mt = 0; mt < 2; mt++) {
                uint32_t ad = SWZ(aRowB + mt * 2048 + kk * 32);
                LDSM4(ah[mt], sAh + ad);
                LDSM4(al[mt], sAl + ad);
            }
#pragma unroll
            for (int p = 0; p < 4; p++) {       // pairs of n-tiles
                uint32_t bh[4], bl[4];
                uint32_t bd = SWZ(bRowB + p * 2048 + kk * 32);
                LDSM4(bh, sBh + bd);
                LDSM4(bl, sBl + bd);
#pragma unroll
                for (int mt = 0; mt < 2; mt++) {
#pragma unroll
                    for (int q = 0; q < 2; q++) {
                        float* c = acc[mt][p * 2 + q];
                        MMA(c, ah[mt], bh + q * 2);
                        MMA(c, ah[mt], bl + q * 2);
                        MMA(c, al[mt], bh + q * 2);
                    }
                }
            }
        }
    }

    // epilogue: c0,c1 -> (row tr, col tc/tc+1); c2,c3 -> row tr+8
    const int tr = lane >> 2, tc = (lane & 3) * 2;
#pragma unroll
    for (int mt = 0; mt < 2; mt++) {
        int r0 = m0 + m_off + mt * 16 + tr;
#pragma unroll
        for (int nt = 0; nt < 8; nt++) {
            int c = n0 + n_off + nt * 8 + tc;
            float b0v = 0.f, b1v = 0.f;
            if (bias) { b0v = bias[c]; b1v = bias[c + 1]; }
            float v0 = acc[mt][nt][0] + b0v;
            float v1 = acc[mt][nt][1] + b1v;
            float v2 = acc[mt][nt][2] + b0v;
            float v3 = acc[mt][nt][3] + b1v;
            if (relu) {
                v0 = fmaxf(v0, 0.f); v1 = fmaxf(v1, 0.f);
                v2 = fmaxf(v2, 0.f); v3 = fmaxf(v3, 0.f);
            }
            if (r0 < M) {
                float2 w; w.x = v0; w.y = v1;
                *(float2*)(C + (size_t)r0 * Nc + c) = w;
            }
            if (r0 + 8 < M) {
                float2 w; w.x = v2; w.y = v3;
                *(float2*)(C + (size_t)(r0 + 8) * Nc + c) = w;
            }
        }
    }
}

// ---------------------------------------------------------------------------
// fp32 -> bf16 hi/lo split (elementwise)
// ---------------------------------------------------------------------------
__global__ void split_kernel(const float* __restrict__ X,
                             __nv_bfloat16* __restrict__ hi,
                             __nv_bfloat16* __restrict__ lo, int n)
{
    int idx = blockIdx.x * blockDim.x + threadIdx.x;
    for (; idx < n; idx += gridDim.x * blockDim.x) {
        float x = X[idx];
        __nv_bfloat16 h = __float2bfloat16(x);
        hi[idx] = h;
        lo[idx] = __float2bfloat16(x - __bfloat162float(h));
    }
}

// weight transpose + split: W[K,N] -> Wt_hi/lo[N,K]
__global__ void wsplit_kernel(const float* __restrict__ W,
                              __nv_bfloat16* __restrict__ hi,
                              __nv_bfloat16* __restrict__ lo, int K, int N)
{
    int idx = blockIdx.x * blockDim.x + threadIdx.x;
    int total = K * N;
    for (; idx < total; idx += gridDim.x * blockDim.x) {
        int k = idx / N;
        int n = idx - k * N;
        float w = W[idx];
        __nv_bfloat16 h = __float2bfloat16(w);
        hi[(size_t)n * K + k] = h;
        lo[(size_t)n * K + k] = __float2bfloat16(w - __bfloat162float(h));
    }
}

// ---------------------------------------------------------------------------
// alpha kernel: per node i, as[i] = dot(Hs[i,:], a_s), ad[i] = dot(Hd[i,:], a_d)
// ---------------------------------------------------------------------------
__global__ void alpha_kernel(const float* __restrict__ Hs,
                             const float* __restrict__ Hd,
                             const float* __restrict__ a_s,
                             const float* __restrict__ a_d,
                             float* __restrict__ as_out,
                             float* __restrict__ ad_out,
                             int N, int C)
{
    int warp = (blockIdx.x * blockDim.x + threadIdx.x) >> 5;
    int lane = threadIdx.x & 31;
    if (warp >= N) return;
    const float* hs = Hs + (size_t)warp * C;
    const float* hd = Hd + (size_t)warp * C;
    float s1 = 0.f, s2 = 0.f;
    for (int c = lane * 4; c < C; c += 32 * 4) {
        float4 h1 = *(const float4*)(hs + c);
        float4 h2 = *(const float4*)(hd + c);
        float4 w1 = *(const float4*)(a_s + c);
        float4 w2 = *(const float4*)(a_d + c);
        s1 += h1.x*w1.x + h1.y*w1.y + h1.z*w1.z + h1.w*w1.w;
        s2 += h2.x*w2.x + h2.y*w2.y + h2.z*w2.z + h2.w*w2.w;
    }
#pragma unroll
    for (int o = 16; o; o >>= 1) {
        s1 += __shfl_xor_sync(0xFFFFFFFFu, s1, o);
        s2 += __shfl_xor_sync(0xFFFFFFFFu, s2, o);
    }
    if (lane == 0) { as_out[warp] = s1; ad_out[warp] = s2; }
}

// ---------------------------------------------------------------------------
// init kernels
// ---------------------------------------------------------------------------
__global__ void init_ms_kernel(float* __restrict__ m, float* __restrict__ s, int N)
{
    int i = blockIdx.x * blockDim.x + threadIdx.x;
    if (i < N) { m[i] = __int_as_float(0xFF800000); s[i] = 0.f; }
}

__global__ void init_agg_kernel(float* __restrict__ agg, const float* __restrict__ b,
                                int N, int C)
{
    int idx = blockIdx.x * blockDim.x + threadIdx.x;
    int total = N * C;
    for (; idx < total; idx += gridDim.x * blockDim.x)
        agg[idx] = 2.0f * b[idx % C];
}

// ---------------------------------------------------------------------------
// edge passes
// ---------------------------------------------------------------------------
__device__ __forceinline__ float leaky(float v)
{
    return v > 0.f ? v : NEG_SLOPE * v;
}

__device__ __forceinline__ void atomicMaxFloat(float* addr, float val)
{
    if (val >= 0.f) atomicMax((int*)addr, __float_as_int(val));
    else            atomicMin((unsigned int*)addr, __float_as_uint(val));
}

__global__ void edge_max_kernel(const int* __restrict__ src, const int* __restrict__ dst,
                                const float* __restrict__ as, const float* __restrict__ ad,
                                float* __restrict__ m, int E)
{
    int e = blockIdx.x * blockDim.x + threadIdx.x;
    if (e >= E) return;
    int si = src[e], di = dst[e];
    float v = leaky(as[si] + ad[di]);
    atomicMaxFloat(&m[di], v);
}

__global__ void edge_sum_kernel(const int* __restrict__ src, const int* __restrict__ dst,
                                const float* __restrict__ as, const float* __restrict__ ad,
                                const float* __restrict__ m, float* __restrict__ s, int E)
{
    int e = blockIdx.x * blockDim.x + threadIdx.x;
    if (e >= E) return;
    int si = src[e], di = dst[e];
    float v = leaky(as[si] + ad[di]);
    atomicAdd(&s[di], __expf(v - m[di]));
}

__global__ void edge_agg_kernel(const int* __restrict__ src, const int* __restrict__ dst,
                                const float* __restrict__ as, const float* __restrict__ ad,
                                const float* __restrict__ m, const float* __restrict__ s,
                                const float* __restrict__ H, float* __restrict__ agg,
                                int E, int C)
{
    int warp = (blockIdx.x * blockDim.x + threadIdx.x) >> 5;
    int lane = threadIdx.x & 31;
    if (warp >= E) return;
    int si = src[warp], di = dst[warp];
    float v = leaky(as[si] + ad[di]);
    float alpha = __expf(v - m[di]) / (s[di] + SEG_EPS);
    const float4* h4 = (const float4*)(H + (size_t)si * C);
    float* ag = agg + (size_t)di * C;
    int nvec = C >> 2;
    for (int c = lane; c < nvec; c += 32) {
        float4 hv = h4[c];
        atomicAdd(ag + 4 * c + 0, alpha * hv.x);
        atomicAdd(ag + 4 * c + 1, alpha * hv.y);
        atomicAdd(ag + 4 * c + 2, alpha * hv.z);
        atomicAdd(ag + 4 * c + 3, alpha * hv.w);
    }
}

// ---------------------------------------------------------------------------
// host-side helpers
// ---------------------------------------------------------------------------
static void run_tc_gemm(const __nv_bfloat16* Ahi, const __nv_bfloat16* Alo,
                        const __nv_bfloat16* Bhi, const __nv_bfloat16* Blo,
                        float* C, int M, int Nc, int K, const float* bias, int relu)
{
    dim3 grid(Nc / 128, (M + 127) / 128);
    hmma_gemm_kernel<<<grid, 256, GSM_TOTAL>>>(Ahi, Alo, Bhi, Blo, C, M, Nc, K, bias, relu);
}

static void run_edge_softmax_agg(const int* ei, const float* asrc, const float* adst,
                                 float* m, float* s, const float* H, float* agg, int C)
{
    const int* src = ei;
    const int* dst = ei + EE;
    int nb1 = (EE + 255) / 256;
    init_ms_kernel<<<(NN + 255) / 256, 256>>>(m, s, NN);
    edge_max_kernel<<<nb1, 256>>>(src, dst, asrc, adst, m, EE);
    edge_sum_kernel<<<nb1, 256>>>(src, dst, asrc, adst, m, s, EE);
    int nbw = ((EE * 32) + 255) / 256;
    edge_agg_kernel<<<nbw, 256>>>(src, dst, asrc, adst, m, s, H, agg, EE, C);
}

extern "C" void kernel_launch(void* const* d_in, const int* in_sizes, int n_in,
                              void* d_out, int out_size)
{
    const float* x      = (const float*)d_in[0];
    const int*   ei1    = (const int*)  d_in[1];
    const int*   ei2    = (const int*)  d_in[2];
    const float* W1_src = (const float*)d_in[3];
    const float* W1_dst = (const float*)d_in[4];
    const float* a1_src = (const float*)d_in[5];
    const float* a1_dst = (const float*)d_in[6];
    const float* b1     = (const float*)d_in[7];
    const float* Wl1    = (const float*)d_in[8];
    const float* bl1    = (const float*)d_in[9];
    const float* W2_src = (const float*)d_in[10];
    const float* W2_dst = (const float*)d_in[11];
    const float* a2_src = (const float*)d_in[12];
    const float* a2_dst = (const float*)d_in[13];
    const float* b2     = (const float*)d_in[14];
    const float* Wl2    = (const float*)d_in[15];
    const float* bl2    = (const float*)d_in[16];
    float* out = (float*)d_out;

    float *H1s, *H1d, *A1, *Hm, *H2s, *H2d, *A2, *as_, *ad_, *m_, *s_;
    __nv_bfloat16 *xhi, *xlo, *wahi, *walo, *wbhi, *wblo;
    cudaGetSymbolAddress((void**)&H1s, g_H1src);
    cudaGetSymbolAddress((void**)&H1d, g_H1dst);
    cudaGetSymbolAddress((void**)&A1,  g_agg1);
    cudaGetSymbolAddress((void**)&Hm,  g_h);
    cudaGetSymbolAddress((void**)&H2s, g_H2src);
    cudaGetSymbolAddress((void**)&H2d, g_H2dst);
    cudaGetSymbolAddress((void**)&A2,  g_agg2);
    cudaGetSymbolAddress((void**)&as_, g_asrc);
    cudaGetSymbolAddress((void**)&ad_, g_adst);
    cudaGetSymbolAddress((void**)&m_,  g_m);
    cudaGetSymbolAddress((void**)&s_,  g_s);
    cudaGetSymbolAddress((void**)&xhi,  g_xhi);
    cudaGetSymbolAddress((void**)&xlo,  g_xlo);
    cudaGetSymbolAddress((void**)&wahi, g_wahi);
    cudaGetSymbolAddress((void**)&walo, g_walo);
    cudaGetSymbolAddress((void**)&wbhi, g_wbhi);
    cudaGetSymbolAddress((void**)&wblo, g_wblo);

    cudaFuncSetAttribute(hmma_gemm_kernel,
                         cudaFuncAttributeMaxDynamicSharedMemorySize, GSM_TOTAL);

    // ---- Layer 1 projections: H1s = x@W1_src, H1d = x@W1_dst ----
    wsplit_kernel<<<512, 256>>>(W1_src, wahi, walo, DD, HH);
    wsplit_kernel<<<512, 256>>>(W1_dst, wbhi, wblo, DD, HH);
    split_kernel<<<2048, 256>>>(x, xhi, xlo, NN * DD);
    run_tc_gemm(xhi, xlo, wahi, walo, H1s, NN, HH, DD, nullptr, 0);
    run_tc_gemm(xhi, xlo, wbhi, wblo, H1d, NN, HH, DD, nullptr, 0);

    alpha_kernel<<<((NN * 32) + 255) / 256, 256>>>(H1s, H1d, a1_src, a1_dst, as_, ad_, NN, HH);
    init_agg_kernel<<<2048, 256>>>(A1, b1, NN, HH);
    run_edge_softmax_agg(ei1, as_, ad_, m_, s_, H1s, A1, HH);
    run_edge_softmax_agg(ei2, as_, ad_, m_, s_, H1s, A1, HH);

    // ---- lin1 + relu: Hm = relu(A1 @ Wl1 + bl1) ----
    wsplit_kernel<<<512, 256>>>(Wl1, wahi, walo, HH, HH);
    split_kernel<<<2048, 256>>>(A1, xhi, xlo, NN * HH);
    run_tc_gemm(xhi, xlo, wahi, walo, Hm, NN, HH, HH, bl1, 1);

    // ---- Layer 2 projections ----
    wsplit_kernel<<<512, 256>>>(W2_src, wahi, walo, HH, OO);
    wsplit_kernel<<<512, 256>>>(W2_dst, wbhi, wblo, HH, OO);
    split_kernel<<<2048, 256>>>(Hm, xhi, xlo, NN * HH);
    run_tc_gemm(xhi, xlo, wahi, walo, H2s, NN, OO, HH, nullptr, 0);
    run_tc_gemm(xhi, xlo, wbhi, wblo, H2d, NN, OO, HH, nullptr, 0);

    alpha_kernel<<<((NN * 32) + 255) / 256, 256>>>(H2s, H2d, a2_src, a2_dst, as_, ad_, NN, OO);
    init_agg_kernel<<<2048, 256>>>(A2, b2, NN, OO);
    run_edge_softmax_agg(ei1, as_, ad_, m_, s_, H2s, A2, OO);
    run_edge_softmax_agg(ei2, as_, ad_, m_, s_, H2s, A2, OO);

    // ---- lin2 -> output ----
    wsplit_kernel<<<512, 256>>>(Wl2, wahi, walo, OO, OO);
    split_kernel<<<2048, 256>>>(A2, xhi, xlo, NN * OO);
    run_tc_gemm(xhi, xlo, wahi, walo, out, NN, OO, OO, bl2, 0);
}

// round 9
// speedup vs baseline: 2.1966x; 1.2702x over previous
#include <cuda_runtime.h>
#include <cuda_bf16.h>
#include <cstdint>
#include <math.h>

// ---------------------------------------------------------------------------
// Two-hop GAT: fixed shapes
// ---------------------------------------------------------------------------
#define NN 50000
#define DD 512
#define HH 512
#define OO 256
#define EE 150000
#define NEG_SLOPE 0.2f
#define SEG_EPS 1e-16f

// ---------------------------------------------------------------------------
// Static device scratch (no allocations allowed)
// ---------------------------------------------------------------------------
__device__ float g_H1src[(size_t)NN * HH];
__device__ float g_H1dst[(size_t)NN * HH];
__device__ float g_agg1 [(size_t)NN * HH];
__device__ float g_h    [(size_t)NN * HH];
__device__ float g_H2src[(size_t)NN * OO];
__device__ float g_H2dst[(size_t)NN * OO];
__device__ float g_agg2 [(size_t)NN * OO];
__device__ float g_asrc [NN];
__device__ float g_adst [NN];
// bf16 split scratch
__device__ __nv_bfloat16 g_xhi[(size_t)NN * HH];
__device__ __nv_bfloat16 g_xlo[(size_t)NN * HH];
__device__ __nv_bfloat16 g_wahi[HH * HH];
__device__ __nv_bfloat16 g_walo[HH * HH];
__device__ __nv_bfloat16 g_wbhi[HH * HH];
__device__ __nv_bfloat16 g_wblo[HH * HH];
// CSR scratch (built once per launch, reused by both layers)
__device__ int g_deg [NN];
__device__ int g_rp1 [NN + 1];
__device__ int g_rp2 [NN + 1];
__device__ int g_eid1[EE];
__device__ int g_eid2[EE];

// ---------------------------------------------------------------------------
// MMA / ldmatrix / cp.async primitives (arch-portable PTX)
// ---------------------------------------------------------------------------
#define SWZ(o) ((o) ^ (((o) >> 3) & 0x70))

#define LDSM4(r, addr) \
    asm volatile("ldmatrix.sync.aligned.m8n8.x4.shared.b16 {%0,%1,%2,%3}, [%4];" \
        : "=r"((r)[0]), "=r"((r)[1]), "=r"((r)[2]), "=r"((r)[3]) : "r"(addr))

#define MMA(c, a, b) \
    asm volatile("mma.sync.aligned.m16n8k16.row.col.f32.bf16.bf16.f32 " \
        "{%0,%1,%2,%3}, {%4,%5,%6,%7}, {%8,%9}, {%0,%1,%2,%3};" \
        : "+f"((c)[0]), "+f"((c)[1]), "+f"((c)[2]), "+f"((c)[3]) \
        : "r"((a)[0]), "r"((a)[1]), "r"((a)[2]), "r"((a)[3]), \
          "r"((b)[0]), "r"((b)[1]))

#define CPASYNC(dst, src, vsz) \
    asm volatile("cp.async.cg.shared.global [%0], [%1], 16, %2;" \
        :: "r"(dst), "l"(src), "r"(vsz))
#define CP_COMMIT() asm volatile("cp.async.commit_group;" ::: "memory")
#define CP_WAIT1()  asm volatile("cp.async.wait_group 1;" ::: "memory")
#define CP_WAIT0()  asm volatile("cp.async.wait_group 0;" ::: "memory")

__device__ __forceinline__ uint32_t smem_u32(const void* p) {
    uint32_t a;
    asm("{ .reg .u64 t; cvta.to.shared.u64 t, %1; cvt.u32.u64 %0, t; }"
        : "=r"(a) : "l"(p));
    return a;
}

// ---------------------------------------------------------------------------
// Pipelined split-bf16 HMMA GEMM: C[M,Nc] = A[M,K] @ Bt[Nc,K]^T (+bias,relu)
// CTA tile 128x256, warp tile 64x64 (8 warps, 256 thr), BK=64.
// 2-stage cp.async pipeline; stage = Ahi16K | Alo16K | Bhi32K | Blo32K = 96KB.
// ---------------------------------------------------------------------------
#define STG 98304
#define GSM_TOTAL (2 * STG)

__global__ __launch_bounds__(256, 1)
void hmma_gemm_pipe(const __nv_bfloat16* __restrict__ Ahi,
                    const __nv_bfloat16* __restrict__ Alo,
                    const __nv_bfloat16* __restrict__ Bhi,
                    const __nv_bfloat16* __restrict__ Blo,
                    float* __restrict__ C, int M, int Nc, int K,
                    const float* __restrict__ bias, int relu)
{
    extern __shared__ __align__(128) char smem[];
    const uint32_t sb = smem_u32(smem);

    const int tid  = threadIdx.x;
    const int lane = tid & 31;
    const int wid  = tid >> 5;
    const int m_off = (wid & 1) * 64;
    const int n_off = (wid >> 1) * 64;
    const int m0 = blockIdx.y * 128, n0 = blockIdx.x * 256;

    float acc[4][8][4];
#pragma unroll
    for (int i = 0; i < 4; i++)
#pragma unroll
        for (int j = 0; j < 8; j++)
#pragma unroll
            for (int l = 0; l < 4; l++) acc[i][j][l] = 0.0f;

    // loader assignment: thread pair per row; 4 x 16B units each
    const int lr = tid >> 1, lh = tid & 1;
    const uint32_t av16 = (m0 + lr) < M ? 16u : 0u;
    const uint4* gAh = (const uint4*)(Ahi + (size_t)(av16 ? m0 + lr : 0) * K) + lh * 4;
    const uint4* gAl = (const uint4*)(Alo + (size_t)(av16 ? m0 + lr : 0) * K) + lh * 4;
    const uint4* gB0h = (const uint4*)(Bhi + (size_t)(n0 + lr) * K) + lh * 4;
    const uint4* gB1h = (const uint4*)(Bhi + (size_t)(n0 + 128 + lr) * K) + lh * 4;
    const uint4* gB0l = (const uint4*)(Blo + (size_t)(n0 + lr) * K) + lh * 4;
    const uint4* gB1l = (const uint4*)(Blo + (size_t)(n0 + 128 + lr) * K) + lh * 4;

    uint32_t du[4];
#pragma unroll
    for (int i = 0; i < 4; i++)
        du[i] = SWZ((uint32_t)lr * 128 + (lh * 4 + i) * 16);

    // ldmatrix per-lane base byte offsets
    const uint32_t aRowB = (uint32_t)(m_off + (lane & 15)) * 128
                         + ((lane >> 4) & 1) * 16;
    const uint32_t bRowB = (uint32_t)(n_off + (lane & 7) + ((lane >> 4) & 1) * 8) * 128
                         + ((lane >> 3) & 1) * 16;

    const int nkt = K >> 6;

#define ISSUE_STAGE(stbase, kt) do {                                          \
    int kb = (kt) * 8;                                                        \
    uint32_t s0 = sb + (stbase);                                              \
    _Pragma("unroll")                                                         \
    for (int i = 0; i < 4; i++) {                                             \
        CPASYNC(s0 + du[i],              gAh + kb + i, av16);                 \
        CPASYNC(s0 + 16384 + du[i],      gAl + kb + i, av16);                 \
        CPASYNC(s0 + 32768 + du[i],      gB0h + kb + i, 16u);                 \
        CPASYNC(s0 + 32768 + 16384 + du[i], gB1h + kb + i, 16u);              \
        CPASYNC(s0 + 65536 + du[i],      gB0l + kb + i, 16u);                 \
        CPASYNC(s0 + 65536 + 16384 + du[i], gB1l + kb + i, 16u);              \
    }                                                                         \
} while (0)

    ISSUE_STAGE(0, 0);
    CP_COMMIT();

    for (int kt = 0; kt < nkt; ++kt) {
        const uint32_t st = sb + (kt & 1) * STG;
        if (kt + 1 < nkt) {
            ISSUE_STAGE(((kt + 1) & 1) * STG, kt + 1);
            CP_COMMIT();
            CP_WAIT1();
        } else {
            CP_WAIT0();
        }
        __syncthreads();

#pragma unroll
        for (int kk = 0; kk < 4; ++kk) {
            uint32_t ah[4][4], al[4][4];
#pragma unroll
            for (int mt = 0; mt < 4; mt++) {
                uint32_t ad = SWZ(aRowB + mt * 2048 + kk * 32);
                LDSM4(ah[mt], st + ad);
                LDSM4(al[mt], st + 16384 + ad);
            }
#pragma unroll
            for (int p = 0; p < 4; p++) {
                uint32_t bh[4], bl[4];
                uint32_t bd = SWZ(bRowB + p * 2048 + kk * 32);
                LDSM4(bh, st + 32768 + bd);
                LDSM4(bl, st + 65536 + bd);
#pragma unroll
                for (int mt = 0; mt < 4; mt++) {
#pragma unroll
                    for (int q = 0; q < 2; q++) {
                        float* c = acc[mt][p * 2 + q];
                        MMA(c, ah[mt], bh + q * 2);
                        MMA(c, ah[mt], bl + q * 2);
                        MMA(c, al[mt], bh + q * 2);
                    }
                }
            }
        }
        __syncthreads();
    }

    // epilogue
    const int tr = lane >> 2, tc = (lane & 3) * 2;
#pragma unroll
    for (int mt = 0; mt < 4; mt++) {
        int r0 = m0 + m_off + mt * 16 + tr;
#pragma unroll
        for (int nt = 0; nt < 8; nt++) {
            int c = n0 + n_off + nt * 8 + tc;
            float b0v = 0.f, b1v = 0.f;
            if (bias) { b0v = bias[c]; b1v = bias[c + 1]; }
            float v0 = acc[mt][nt][0] + b0v;
            float v1 = acc[mt][nt][1] + b1v;
            float v2 = acc[mt][nt][2] + b0v;
            float v3 = acc[mt][nt][3] + b1v;
            if (relu) {
                v0 = fmaxf(v0, 0.f); v1 = fmaxf(v1, 0.f);
                v2 = fmaxf(v2, 0.f); v3 = fmaxf(v3, 0.f);
            }
            if (r0 < M) {
                float2 w; w.x = v0; w.y = v1;
                *(float2*)(C + (size_t)r0 * Nc + c) = w;
            }
            if (r0 + 8 < M) {
                float2 w; w.x = v2; w.y = v3;
                *(float2*)(C + (size_t)(r0 + 8) * Nc + c) = w;
            }
        }
    }
}

// ---------------------------------------------------------------------------
// fp32 -> bf16 hi/lo split
// ---------------------------------------------------------------------------
__global__ void split_kernel(const float* __restrict__ X,
                             __nv_bfloat16* __restrict__ hi,
                             __nv_bfloat16* __restrict__ lo, int n)
{
    int idx = blockIdx.x * blockDim.x + threadIdx.x;
    for (; idx < n; idx += gridDim.x * blockDim.x) {
        float x = X[idx];
        __nv_bfloat16 h = __float2bfloat16(x);
        hi[idx] = h;
        lo[idx] = __float2bfloat16(x - __bfloat162float(h));
    }
}

// weight transpose + split: W[K,N] -> Wt_hi/lo[N,K]
__global__ void wsplit_kernel(const float* __restrict__ W,
                              __nv_bfloat16* __restrict__ hi,
                              __nv_bfloat16* __restrict__ lo, int K, int N)
{
    int idx = blockIdx.x * blockDim.x + threadIdx.x;
    int total = K * N;
    for (; idx < total; idx += gridDim.x * blockDim.x) {
        int k = idx / N;
        int n = idx - k * N;
        float w = W[idx];
        __nv_bfloat16 h = __float2bfloat16(w);
        hi[(size_t)n * K + k] = h;
        lo[(size_t)n * K + k] = __float2bfloat16(w - __bfloat162float(h));
    }
}

// ---------------------------------------------------------------------------
// alpha kernel
// ---------------------------------------------------------------------------
__global__ void alpha_kernel(const float* __restrict__ Hs,
                             const float* __restrict__ Hd,
                             const float* __restrict__ a_s,
                             const float* __restrict__ a_d,
                             float* __restrict__ as_out,
                             float* __restrict__ ad_out,
                             int N, int C)
{
    int warp = (blockIdx.x * blockDim.x + threadIdx.x) >> 5;
    int lane = threadIdx.x & 31;
    if (warp >= N) return;
    const float* hs = Hs + (size_t)warp * C;
    const float* hd = Hd + (size_t)warp * C;
    float s1 = 0.f, s2 = 0.f;
    for (int c = lane * 4; c < C; c += 32 * 4) {
        float4 h1 = *(const float4*)(hs + c);
        float4 h2 = *(const float4*)(hd + c);
        float4 w1 = *(const float4*)(a_s + c);
        float4 w2 = *(const float4*)(a_d + c);
        s1 += h1.x*w1.x + h1.y*w1.y + h1.z*w1.z + h1.w*w1.w;
        s2 += h2.x*w2.x + h2.y*w2.y + h2.z*w2.z + h2.w*w2.w;
    }
#pragma unroll
    for (int o = 16; o; o >>= 1) {
        s1 += __shfl_xor_sync(0xFFFFFFFFu, s1, o);
        s2 += __shfl_xor_sync(0xFFFFFFFFu, s2, o);
    }
    if (lane == 0) { as_out[warp] = s1; ad_out[warp] = s2; }
}

// ---------------------------------------------------------------------------
// CSR build: zero / hist / scan / fill
// ---------------------------------------------------------------------------
__global__ void zero_int_kernel(int* __restrict__ p, int n)
{
    int i = blockIdx.x * blockDim.x + threadIdx.x;
    if (i < n) p[i] = 0;
}

__global__ void hist_kernel(const int* __restrict__ dst, int* __restrict__ deg, int E)
{
    int e = blockIdx.x * blockDim.x + threadIdx.x;
    if (e < E) atomicAdd(&deg[dst[e]], 1);
}

__global__ void scan_kernel(const int* __restrict__ deg, int* __restrict__ rp)
{
    __shared__ int sd[1024];
    __shared__ int carry;
    int tid = threadIdx.x;
    if (tid == 0) { carry = 0; rp[0] = 0; }
    __syncthreads();
    for (int base = 0; base < NN; base += 1024) {
        int i = base + tid;
        int v = (i < NN) ? deg[i] : 0;
        sd[tid] = v;
        __syncthreads();
        for (int off = 1; off < 1024; off <<= 1) {
            int t = (tid >= off) ? sd[tid - off] : 0;
            __syncthreads();
            sd[tid] += t;
            __syncthreads();
        }
        int c = carry;
        if (i < NN) rp[i + 1] = sd[tid] + c;
        __syncthreads();
        if (tid == 1023) carry = c + sd[1023];
        __syncthreads();
    }
}

__global__ void fill_kernel(const int* __restrict__ dst, const int* __restrict__ rp,
                            int* __restrict__ fill, int* __restrict__ eid, int E)
{
    int e = blockIdx.x * blockDim.x + threadIdx.x;
    if (e >= E) return;
    int d = dst[e];
    int pos = rp[d] + atomicAdd(&fill[d], 1);
    eid[pos] = e;
}

// ---------------------------------------------------------------------------
// gather kernel: warp per dst; both edge sets; writes out = agg1+agg2+2b
// ---------------------------------------------------------------------------
__device__ __forceinline__ float leaky(float v)
{
    return v > 0.f ? v : NEG_SLOPE * v;
}

template <int C>
__device__ __forceinline__ void gather_set(
    int d, int lane, float ad_d,
    const int* __restrict__ rp, const int* __restrict__ eid,
    const int* __restrict__ src, const float* __restrict__ as,
    const float4* __restrict__ H4, float4* acc)
{
    int b0 = rp[d], b1 = rp[d + 1];
    if (b1 <= b0) return;
    float mx = -1e30f;
    for (int i = b0; i < b1; i++) {
        float v = leaky(as[src[eid[i]]] + ad_d);
        mx = fmaxf(mx, v);
    }
    float s = 0.f;
    for (int i = b0; i < b1; i++) {
        float v = leaky(as[src[eid[i]]] + ad_d);
        s += __expf(v - mx);
    }
    float rinv = 1.f / (s + SEG_EPS);
    for (int i = b0; i < b1; i++) {
        int sidx = src[eid[i]];
        float v = leaky(as[sidx] + ad_d);
        float w = __expf(v - mx) * rinv;
        const float4* hrow = H4 + (size_t)sidx * (C / 4);
#pragma unroll
        for (int j = 0; j < C / 128; j++) {
            float4 h = hrow[j * 32 + lane];
            acc[j].x += w * h.x;
            acc[j].y += w * h.y;
            acc[j].z += w * h.z;
            acc[j].w += w * h.w;
        }
    }
}

template <int C>
__global__ void gat_gather_kernel(
    const int* __restrict__ rp1, const int* __restrict__ eid1, const int* __restrict__ src1,
    const int* __restrict__ rp2, const int* __restrict__ eid2, const int* __restrict__ src2,
    const float* __restrict__ as, const float* __restrict__ ad,
    const float* __restrict__ H, const float* __restrict__ bias,
    float* __restrict__ out)
{
    int d = (blockIdx.x * blockDim.x + threadIdx.x) >> 5;
    int lane = threadIdx.x & 31;
    if (d >= NN) return;

    float4 acc[C / 128];
#pragma unroll
    for (int j = 0; j < C / 128; j++) acc[j] = make_float4(0.f, 0.f, 0.f, 0.f);

    float ad_d = ad[d];
    const float4* H4 = (const float4*)H;

    gather_set<C>(d, lane, ad_d, rp1, eid1, src1, as, H4, acc);
    gather_set<C>(d, lane, ad_d, rp2, eid2, src2, as, H4, acc);

    const float4* b4 = (const float4*)bias;
    float4* o4 = (float4*)(out + (size_t)d * C);
#pragma unroll
    for (int j = 0; j < C / 128; j++) {
        float4 b = b4[j * 32 + lane];
        float4 v;
        v.x = acc[j].x + 2.f * b.x;
        v.y = acc[j].y + 2.f * b.y;
        v.z = acc[j].z + 2.f * b.z;
        v.w = acc[j].w + 2.f * b.w;
        o4[j * 32 + lane] = v;
    }
}

// ---------------------------------------------------------------------------
// host-side helpers
// ---------------------------------------------------------------------------
static void run_gemm(const __nv_bfloat16* Ahi, const __nv_bfloat16* Alo,
                     const __nv_bfloat16* Bhi, const __nv_bfloat16* Blo,
                     float* C, int M, int Nc, int K, const float* bias, int relu)
{
    dim3 grid(Nc / 256, (M + 127) / 128);
    hmma_gemm_pipe<<<grid, 256, GSM_TOTAL>>>(Ahi, Alo, Bhi, Blo, C, M, Nc, K, bias, relu);
}

static void build_csr(const int* dst, int* deg, int* rp, int* eid)
{
    zero_int_kernel<<<(NN + 255) / 256, 256>>>(deg, NN);
    hist_kernel<<<(EE + 255) / 256, 256>>>(dst, deg, EE);
    scan_kernel<<<1, 1024>>>(deg, rp);
    zero_int_kernel<<<(NN + 255) / 256, 256>>>(deg, NN);
    fill_kernel<<<(EE + 255) / 256, 256>>>(dst, rp, deg, eid, EE);
}

extern "C" void kernel_launch(void* const* d_in, const int* in_sizes, int n_in,
                              void* d_out, int out_size)
{
    const float* x      = (const float*)d_in[0];
    const int*   ei1    = (const int*)  d_in[1];
    const int*   ei2    = (const int*)  d_in[2];
    const float* W1_src = (const float*)d_in[3];
    const float* W1_dst = (const float*)d_in[4];
    const float* a1_src = (const float*)d_in[5];
    const float* a1_dst = (const float*)d_in[6];
    const float* b1     = (const float*)d_in[7];
    const float* Wl1    = (const float*)d_in[8];
    const float* bl1    = (const float*)d_in[9];
    const float* W2_src = (const float*)d_in[10];
    const float* W2_dst = (const float*)d_in[11];
    const float* a2_src = (const float*)d_in[12];
    const float* a2_dst = (const float*)d_in[13];
    const float* b2     = (const float*)d_in[14];
    const float* Wl2    = (const float*)d_in[15];
    const float* bl2    = (const float*)d_in[16];
    float* out = (float*)d_out;

    const int* src1 = ei1;
    const int* dst1 = ei1 + EE;
    const int* src2 = ei2;
    const int* dst2 = ei2 + EE;

    float *H1s, *H1d, *A1, *Hm, *H2s, *H2d, *A2, *as_, *ad_;
    __nv_bfloat16 *xhi, *xlo, *wahi, *walo, *wbhi, *wblo;
    int *deg, *rp1, *rp2, *eid1, *eid2;
    cudaGetSymbolAddress((void**)&H1s, g_H1src);
    cudaGetSymbolAddress((void**)&H1d, g_H1dst);
    cudaGetSymbolAddress((void**)&A1,  g_agg1);
    cudaGetSymbolAddress((void**)&Hm,  g_h);
    cudaGetSymbolAddress((void**)&H2s, g_H2src);
    cudaGetSymbolAddress((void**)&H2d, g_H2dst);
    cudaGetSymbolAddress((void**)&A2,  g_agg2);
    cudaGetSymbolAddress((void**)&as_, g_asrc);
    cudaGetSymbolAddress((void**)&ad_, g_adst);
    cudaGetSymbolAddress((void**)&xhi,  g_xhi);
    cudaGetSymbolAddress((void**)&xlo,  g_xlo);
    cudaGetSymbolAddress((void**)&wahi, g_wahi);
    cudaGetSymbolAddress((void**)&walo, g_walo);
    cudaGetSymbolAddress((void**)&wbhi, g_wbhi);
    cudaGetSymbolAddress((void**)&wblo, g_wblo);
    cudaGetSymbolAddress((void**)&deg,  g_deg);
    cudaGetSymbolAddress((void**)&rp1,  g_rp1);
    cudaGetSymbolAddress((void**)&rp2,  g_rp2);
    cudaGetSymbolAddress((void**)&eid1, g_eid1);
    cudaGetSymbolAddress((void**)&eid2, g_eid2);

    cudaFuncSetAttribute(hmma_gemm_pipe,
                         cudaFuncAttributeMaxDynamicSharedMemorySize, GSM_TOTAL);

    // ---- CSR for both edge sets (used by both layers) ----
    build_csr(dst1, deg, rp1, eid1);
    build_csr(dst2, deg, rp2, eid2);

    // ---- Layer 1 projections ----
    wsplit_kernel<<<512, 256>>>(W1_src, wahi, walo, DD, HH);
    wsplit_kernel<<<512, 256>>>(W1_dst, wbhi, wblo, DD, HH);
    split_kernel<<<2048, 256>>>(x, xhi, xlo, NN * DD);
    run_gemm(xhi, xlo, wahi, walo, H1s, NN, HH, DD, nullptr, 0);
    run_gemm(xhi, xlo, wbhi, wblo, H1d, NN, HH, DD, nullptr, 0);

    alpha_kernel<<<((NN * 32) + 255) / 256, 256>>>(H1s, H1d, a1_src, a1_dst, as_, ad_, NN, HH);
    gat_gather_kernel<HH><<<((NN * 32) + 255) / 256, 256>>>(
        rp1, eid1, src1, rp2, eid2, src2, as_, ad_, H1s, b1, A1);

    // ---- lin1 + relu ----
    wsplit_kernel<<<512, 256>>>(Wl1, wahi, walo, HH, HH);
    split_kernel<<<2048, 256>>>(A1, xhi, xlo, NN * HH);
    run_gemm(xhi, xlo, wahi, walo, Hm, NN, HH, HH, bl1, 1);

    // ---- Layer 2 projections ----
    wsplit_kernel<<<512, 256>>>(W2_src, wahi, walo, HH, OO);
    wsplit_kernel<<<512, 256>>>(W2_dst, wbhi, wblo, HH, OO);
    split_kernel<<<2048, 256>>>(Hm, xhi, xlo, NN * HH);
    run_gemm(xhi, xlo, wahi, walo, H2s, NN, OO, HH, nullptr, 0);
    run_gemm(xhi, xlo, wbhi, wblo, H2d, NN, OO, HH, nullptr, 0);

    alpha_kernel<<<((NN * 32) + 255) / 256, 256>>>(H2s, H2d, a2_src, a2_dst, as_, ad_, NN, OO);
    gat_gather_kernel<OO><<<((NN * 32) + 255) / 256, 256>>>(
        rp1, eid1, src1, rp2, eid2, src2, as_, ad_, H2s, b2, A2);

    // ---- lin2 -> output ----
    wsplit_kernel<<<512, 256>>>(Wl2, wahi, walo, OO, OO);
    split_kernel<<<2048, 256>>>(A2, xhi, xlo, NN * OO);
    run_gemm(xhi, xlo, wahi, walo, out, NN, OO, OO, bl2, 0);
}